// round 4
// baseline (speedup 1.0000x reference)
#include <cuda_runtime.h>
#include <cuda_bf16.h>
#include <math.h>
#include <stdint.h>

#define B_ 2
#define S_ 1024
#define E_ 1024
#define D_ 2048
#define H_ 8
#define KV_ 4
#define HD_ 256
#define WINDOW_ 512
#define SOFTCAP_ 50.0f
#define SCALE_ 0.0625f   /* 256^-0.5 */

// ---------------- scratch (device globals: allocation-free) ----------------
__device__ float g_q     [B_*S_*H_ *HD_];   // [B*S, H, HD]
__device__ float g_kself [B_*S_*KV_*HD_];
__device__ float g_vself [B_*S_*KV_*HD_];
__device__ float g_kcross[B_*E_*KV_*HD_];
__device__ float g_vcross[B_*E_*KV_*HD_];
__device__ float g_attn  [B_*S_*H_ *HD_];
__device__ int   g_seg   [B_*S_];
// bf16 split buffers (activations [M,K] row-major, weights transposed [N,K])
__device__ __nv_bfloat16 g_act_hi[2048*2048];
__device__ __nv_bfloat16 g_act_lo[2048*2048];
__device__ __nv_bfloat16 g_wt_hi [2048*2048];
__device__ __nv_bfloat16 g_wt_lo [2048*2048];

// ================== PTX helpers (baseline-ISA only, no tcgen05) ============
__device__ __forceinline__ uint32_t smem_u32(const void* p){
    uint32_t a;
    asm("{ .reg .u64 t; cvta.to.shared.u64 t, %1; cvt.u32.u64 %0, t; }" : "=r"(a) : "l"(p));
    return a;
}
__device__ __forceinline__ void cpa16(uint32_t s, const void* g){
    asm volatile("cp.async.cg.shared.global [%0], [%1], 16;" :: "r"(s), "l"(g) : "memory");
}
__device__ __forceinline__ void cp_commit(){
    asm volatile("cp.async.commit_group;" ::: "memory");
}
template<int N> __device__ __forceinline__ void cp_wait(){
    asm volatile("cp.async.wait_group %0;" :: "n"(N) : "memory");
}
#define MMA16816(d, a, b) \
    asm volatile("mma.sync.aligned.m16n8k16.row.col.f32.bf16.bf16.f32 " \
        "{%0,%1,%2,%3},{%4,%5,%6,%7},{%8,%9},{%0,%1,%2,%3};" \
        : "+f"((d)[0]), "+f"((d)[1]), "+f"((d)[2]), "+f"((d)[3]) \
        : "r"((a)[0]), "r"((a)[1]), "r"((a)[2]), "r"((a)[3]), \
          "r"((b)[0]), "r"((b)[1]))

// ================== HMMA bf16x3 GEMM ==================
// C[M,N] = A[M,K] @ Bt[N,K]^T ; A,Bt as bf16 hi/lo splits, K-contiguous.
// BM=BN=128, BK=32, 4-stage cp.async pipeline, 256 threads (8 warps, 4x2).
// smem rows padded to 80B (stride 20 words): conflict-free fragment loads.
#define LDROW 80
#define BUFB (128*LDROW)         /* 10240 B: one of {Ah,Al,Bh,Bl} */
#define STG_BYTES (4*BUFB)       /* 40960 B per stage */
#define GEMM_SMEM (4*STG_BYTES)  /* 163840 B */

__global__ __launch_bounds__(256) void gemm_hmma_kernel(
    int M, int N, int K,
    const __nv_bfloat16* __restrict__ Ahi, const __nv_bfloat16* __restrict__ Alo,
    const __nv_bfloat16* __restrict__ Bhi, const __nv_bfloat16* __restrict__ Blo,
    float* __restrict__ C)
{
    extern __shared__ char dsm[];
    const uint32_t sb = smem_u32(dsm);
    const int tid = threadIdx.x;
    const int lane = tid & 31, w = tid >> 5;
    const int g = lane >> 2, tg = lane & 3;
    const int wm = w & 3, wn = w >> 2;
    const int bx = blockIdx.x, by = blockIdx.y;

    const __nv_bfloat16* gp0 = Ahi + (size_t)by * 128 * K;
    const __nv_bfloat16* gp1 = Alo + (size_t)by * 128 * K;
    const __nv_bfloat16* gp2 = Bhi + (size_t)bx * 128 * K;
    const __nv_bfloat16* gp3 = Blo + (size_t)bx * 128 * K;

    float acc[2][8][4];
    #pragma unroll
    for (int mt = 0; mt < 2; mt++)
        #pragma unroll
        for (int nt = 0; nt < 8; nt++)
            #pragma unroll
            for (int i = 0; i < 4; i++) acc[mt][nt][i] = 0.f;

    const int niter = K >> 5;   // BK=32

    // stage loader: 2048 16B-chunks, 8 per thread, coalesced (c = i*256+tid)
    auto load_stage = [&](int stage, int k0){
        #pragma unroll
        for (int i = 0; i < 8; i++){
            int c = i * 256 + tid;
            int r = (c >> 2) & 127;
            int ch = c & 3;
            uint32_t saddr = sb + stage * STG_BYTES + (c >> 9) * BUFB
                           + r * LDROW + ch * 16;
            const __nv_bfloat16* gp = (i < 2) ? gp0 : (i < 4) ? gp1 : (i < 6) ? gp2 : gp3;
            cpa16(saddr, gp + (size_t)r * K + k0 + ch * 8);
        }
        cp_commit();
    };

    load_stage(0, 0);
    load_stage(1, 32);
    load_stage(2, 64);

    for (int it = 0; it < niter; it++){
        cp_wait<2>();
        __syncthreads();
        if (it + 3 < niter) load_stage((it + 3) & 3, (it + 3) * 32);

        const char* st = dsm + (it & 3) * STG_BYTES;
        #pragma unroll
        for (int ks = 0; ks < 32; ks += 16){
            const int acolB = (ks + 2 * tg) * 2;     // byte offset of half col
            uint32_t ah[2][4], al[2][4];
            #pragma unroll
            for (int mt = 0; mt < 2; mt++){
                const char* p = st + (wm * 32 + mt * 16 + g) * LDROW + acolB;
                ah[mt][0] = *(const uint32_t*)(p);
                ah[mt][2] = *(const uint32_t*)(p + 16);
                ah[mt][1] = *(const uint32_t*)(p + 8 * LDROW);
                ah[mt][3] = *(const uint32_t*)(p + 8 * LDROW + 16);
                const char* q = p + BUFB;
                al[mt][0] = *(const uint32_t*)(q);
                al[mt][2] = *(const uint32_t*)(q + 16);
                al[mt][1] = *(const uint32_t*)(q + 8 * LDROW);
                al[mt][3] = *(const uint32_t*)(q + 8 * LDROW + 16);
            }
            uint32_t bh[8][2], bl[8][2];
            #pragma unroll
            for (int nt = 0; nt < 8; nt++){
                const char* p = st + 2 * BUFB + (wn * 64 + nt * 8 + g) * LDROW + acolB;
                bh[nt][0] = *(const uint32_t*)(p);
                bh[nt][1] = *(const uint32_t*)(p + 16);
                const char* q = p + BUFB;
                bl[nt][0] = *(const uint32_t*)(q);
                bl[nt][1] = *(const uint32_t*)(q + 16);
            }
            #pragma unroll
            for (int mt = 0; mt < 2; mt++)
                #pragma unroll
                for (int nt = 0; nt < 8; nt++){
                    MMA16816(acc[mt][nt], ah[mt], bh[nt]);
                    MMA16816(acc[mt][nt], ah[mt], bl[nt]);
                    MMA16816(acc[mt][nt], al[mt], bh[nt]);
                }
        }
    }

    // epilogue
    #pragma unroll
    for (int mt = 0; mt < 2; mt++){
        int r = by * 128 + wm * 32 + mt * 16 + g;
        #pragma unroll
        for (int nt = 0; nt < 8; nt++){
            int c = bx * 128 + wn * 64 + nt * 8 + 2 * tg;
            *(float2*)(C + (size_t)r * N + c)       = make_float2(acc[mt][nt][0], acc[mt][nt][1]);
            *(float2*)(C + (size_t)(r + 8) * N + c) = make_float2(acc[mt][nt][2], acc[mt][nt][3]);
        }
    }
}

// ---------------- fp32 -> bf16 hi/lo split (elementwise) -------------------
__global__ __launch_bounds__(256) void asplit_kernel(
    const float* __restrict__ x, __nv_bfloat16* __restrict__ hi,
    __nv_bfloat16* __restrict__ lo, int n)
{
    int i = (blockIdx.x * 256 + threadIdx.x) * 4;
    if (i >= n) return;
    float4 v = *(const float4*)(x + i);
    float a[4] = {v.x, v.y, v.z, v.w};
    __nv_bfloat16 h[4], l[4];
    #pragma unroll
    for (int j = 0; j < 4; j++){
        h[j] = __float2bfloat16(a[j]);
        l[j] = __float2bfloat16(a[j] - __bfloat162float(h[j]));
    }
    *(__nv_bfloat162*)(hi + i)     = __nv_bfloat162(h[0], h[1]);
    *(__nv_bfloat162*)(hi + i + 2) = __nv_bfloat162(h[2], h[3]);
    *(__nv_bfloat162*)(lo + i)     = __nv_bfloat162(l[0], l[1]);
    *(__nv_bfloat162*)(lo + i + 2) = __nv_bfloat162(l[2], l[3]);
}

// ---------------- weight transpose + split: W[K,N] -> Wt[N,K] bf16 ---------
__global__ __launch_bounds__(256) void wsplit_kernel(
    const float* __restrict__ W, __nv_bfloat16* __restrict__ hi,
    __nv_bfloat16* __restrict__ lo, int K, int N)
{
    __shared__ float t[32][33];
    int n0 = blockIdx.x * 32, k0 = blockIdx.y * 32;
    int tx = threadIdx.x & 31, ty = threadIdx.x >> 5;
    #pragma unroll
    for (int r = 0; r < 32; r += 8)
        t[ty + r][tx] = W[(size_t)(k0 + ty + r) * N + n0 + tx];
    __syncthreads();
    #pragma unroll
    for (int r = 0; r < 32; r += 8){
        float v = t[tx][ty + r];
        __nv_bfloat16 h = __float2bfloat16(v);
        __nv_bfloat16 l = __float2bfloat16(v - __bfloat162float(h));
        size_t o = (size_t)(n0 + ty + r) * K + k0 + tx;
        hi[o] = h; lo[o] = l;
    }
}

// ---------------- segment ids: parallel Hillis-Steele scan ------------------
__global__ __launch_bounds__(1024) void seg_kernel(const int* __restrict__ pos) {
    __shared__ int sh[1024];
    int b = blockIdx.x, i = threadIdx.x;
    int p = pos[b*S_ + i];
    int flag = (i == 0) ? 1 : ((p <= pos[b*S_ + i - 1]) ? 1 : 0);
    sh[i] = flag;
    __syncthreads();
    #pragma unroll
    for (int off = 1; off < 1024; off <<= 1){
        int v = sh[i];
        int add = (i >= off) ? sh[i - off] : 0;
        __syncthreads();
        sh[i] = v + add;
        __syncthreads();
    }
    g_seg[b*S_ + i] = sh[i];
}

// ---------------- fused RMS norm (+ optional RoPE), in place ----------------
__global__ __launch_bounds__(256) void norm_rope_kernel(
    float* __restrict__ buf, const float* __restrict__ nw,
    const float* __restrict__ cs, const float* __restrict__ sn,
    int nheads, int do_rope)
{
    int blk = blockIdx.x;
    int h = blk % nheads;
    int t = blk / nheads;
    float* x = buf + ((size_t)t * nheads + h) * HD_;
    int d = threadIdx.x;
    float v = x[d];
    float ss = v * v;
    __shared__ float red[8];
    #pragma unroll
    for (int o = 16; o; o >>= 1) ss += __shfl_xor_sync(0xffffffffu, ss, o);
    if ((d & 31) == 0) red[d >> 5] = ss;
    __syncthreads();
    float tot = 0.f;
    #pragma unroll
    for (int i = 0; i < 8; i++) tot += red[i];
    float inv = rsqrtf(tot * (1.0f / HD_) + 1e-6f);
    float xn = v * inv * (1.0f + nw[d]);
    if (do_rope) {
        __shared__ float sx[HD_];
        sx[d] = xn;
        __syncthreads();
        float rot = (d < HD_/2) ? -sx[d + HD_/2] : sx[d - HD_/2];
        xn = xn * cs[(size_t)t * HD_ + d] + rot * sn[(size_t)t * HD_ + d];
    }
    x[d] = xn;
}

// ---------------- attention: flash-style, 32 q/block, 32-key tiles ----------
__device__ __forceinline__ float softcap_tanh(float sc){
    // SOFTCAP * tanh(sc/SOFTCAP) via exp identity (fast, ~1e-7 accurate)
    float x2 = fabsf(sc) * (2.0f / SOFTCAP_);
    float e = __expf(-x2);
    float t = __fdividef(1.0f - e, 1.0f + e);
    return copysignf(SOFTCAP_ * t, sc);
}

__global__ __launch_bounds__(256) void attn_kernel(
    const int* __restrict__ dmask, const int* __restrict__ emask)
{
    extern __shared__ float smem[];
    float (*Ks)[HD_] = (float(*)[HD_])smem;
    float (*Vs)[HD_] = (float(*)[HD_])(smem + 32 * HD_);

    int b = blockIdx.z, h = blockIdx.y, qt = blockIdx.x;
    int kv = h >> 1;
    int tid = threadIdx.x;
    int lane = tid & 31, w = tid >> 5;
    int qbase = qt * 32;
    int q0 = qbase + w * 4;

    float qf[4][8], o[4][8];
    float m[4], l[4];
    int myseg[4];
    #pragma unroll
    for (int qi = 0; qi < 4; qi++) {
        const float* qp = g_q + ((size_t)((b*S_ + q0 + qi)*H_ + h)) * HD_;
        #pragma unroll
        for (int e = 0; e < 8; e++) { qf[qi][e] = qp[e*32 + lane]; o[qi][e] = 0.f; }
        m[qi] = -3.0e38f; l[qi] = 0.f;
        myseg[qi] = g_seg[b*S_ + q0 + qi];
    }

    int lo = qbase - (WINDOW_ - 1);
    int t_lo = (lo <= 0) ? 0 : (lo >> 5);
    int nself = qt - t_lo + 1;
    int npass = nself + E_ / 32;

    for (int pass = 0; pass < npass; pass++) {
        bool is_self = pass < nself;
        int jg0, jloc0;
        const float *kb, *vb;
        if (is_self) { jg0 = (t_lo + pass) * 32; jloc0 = jg0; kb = g_kself; vb = g_vself; }
        else { int t = pass - nself; jg0 = S_ + t*32; jloc0 = t*32; kb = g_kcross; vb = g_vcross; }

        __syncthreads();
        #pragma unroll
        for (int r = 0; r < 8; r++) {
            int i = tid + 256 * r;
            int row = i >> 6;
            int c4 = (i & 63) << 2;
            size_t off = ((size_t)((b*1024 + jloc0 + row)*KV_ + kv)) * HD_ + c4;
            *(float4*)&Ks[row][c4] = *(const float4*)(kb + off);
            *(float4*)&Vs[row][c4] = *(const float4*)(vb + off);
        }
        __syncthreads();

        int jg = jg0 + lane;
        bool keyvalid; int segj = 0;
        if (is_self) {
            keyvalid = dmask[b*S_ + jg] != 0;
            segj = g_seg[b*S_ + jg];
        } else {
            keyvalid = emask[b*E_ + (jg - S_)] != 0;
        }

        float sraw[4];
        #pragma unroll
        for (int j = 0; j < 32; j++) {
            float kf[8];
            #pragma unroll
            for (int e = 0; e < 8; e++) kf[e] = Ks[j][e*32 + lane];
            #pragma unroll
            for (int qi = 0; qi < 4; qi++) {
                float d = 0.f;
                #pragma unroll
                for (int e = 0; e < 8; e++) d += qf[qi][e] * kf[e];
                #pragma unroll
                for (int off = 16; off; off >>= 1) d += __shfl_xor_sync(0xffffffffu, d, off);
                if (lane == j) sraw[qi] = d;
            }
        }

        float p[4];
        #pragma unroll
        for (int qi = 0; qi < 4; qi++) {
            int q = q0 + qi;
            float sc = softcap_tanh(sraw[qi] * SCALE_);
            bool valid = keyvalid;
            if (is_self) valid = valid && (jg <= q) && (q - jg < WINDOW_) && (segj == myseg[qi]);
            if (!valid) sc = -1e30f;
            float tm = sc;
            #pragma unroll
            for (int off = 16; off; off >>= 1) tm = fmaxf(tm, __shfl_xor_sync(0xffffffffu, tm, off));
            float mnew = fmaxf(m[qi], tm);
            float corr = __expf(m[qi] - mnew);
            m[qi] = mnew;
            float pp = __expf(sc - mnew);
            p[qi] = pp;
            float ps = pp;
            #pragma unroll
            for (int off = 16; off; off >>= 1) ps += __shfl_xor_sync(0xffffffffu, ps, off);
            l[qi] = l[qi] * corr + ps;
            #pragma unroll
            for (int e = 0; e < 8; e++) o[qi][e] *= corr;
        }

        #pragma unroll
        for (int j = 0; j < 32; j++) {
            float pj0 = __shfl_sync(0xffffffffu, p[0], j);
            float pj1 = __shfl_sync(0xffffffffu, p[1], j);
            float pj2 = __shfl_sync(0xffffffffu, p[2], j);
            float pj3 = __shfl_sync(0xffffffffu, p[3], j);
            #pragma unroll
            for (int e = 0; e < 8; e++) {
                float v = Vs[j][e*32 + lane];
                o[0][e] += pj0 * v;
                o[1][e] += pj1 * v;
                o[2][e] += pj2 * v;
                o[3][e] += pj3 * v;
            }
        }
    }

    #pragma unroll
    for (int qi = 0; qi < 4; qi++) {
        float inv = 1.0f / l[qi];
        float* op = g_attn + ((size_t)((b*S_ + q0 + qi)*H_ + h)) * HD_;
        #pragma unroll
        for (int e = 0; e < 8; e++) op[e*32 + lane] = o[qi][e] * inv;
    }
}

// ---------------- launch ----------------------------------------------------
extern "C" void kernel_launch(void* const* d_in, const int* in_sizes, int n_in,
                              void* d_out, int out_size)
{
    const float* hs   = (const float*)d_in[0];
    const float* enc  = (const float*)d_in[1];
    const float* cosp = (const float*)d_in[2];
    const float* sinp = (const float*)d_in[3];
    const float* wq   = (const float*)d_in[4];
    const float* wk   = (const float*)d_in[5];
    const float* wv   = (const float*)d_in[6];
    const float* wo   = (const float*)d_in[7];
    const float* qnw  = (const float*)d_in[8];
    const float* knw  = (const float*)d_in[9];
    const int*   dmsk = (const int*)d_in[10];
    const int*   emsk = (const int*)d_in[11];
    const int*   pos  = (const int*)d_in[12];
    float* out = (float*)d_out;

    float *gq, *gks, *gvs, *gkc, *gvc, *gat;
    __nv_bfloat16 *ahi, *alo, *whi, *wlo;
    cudaGetSymbolAddress((void**)&gq,  g_q);
    cudaGetSymbolAddress((void**)&gks, g_kself);
    cudaGetSymbolAddress((void**)&gvs, g_vself);
    cudaGetSymbolAddress((void**)&gkc, g_kcross);
    cudaGetSymbolAddress((void**)&gvc, g_vcross);
    cudaGetSymbolAddress((void**)&gat, g_attn);
    cudaGetSymbolAddress((void**)&ahi, g_act_hi);
    cudaGetSymbolAddress((void**)&alo, g_act_lo);
    cudaGetSymbolAddress((void**)&whi, g_wt_hi);
    cudaGetSymbolAddress((void**)&wlo, g_wt_lo);

    cudaFuncSetAttribute(gemm_hmma_kernel,
                         cudaFuncAttributeMaxDynamicSharedMemorySize, GEMM_SMEM);

    const int MT = B_*S_;     // 2048 token rows
    // decoder activations
    asplit_kernel<<<(MT*D_)/1024, 256>>>(hs, ahi, alo, MT*D_);
    // q = hs @ wq
    wsplit_kernel<<<dim3((H_*HD_)/32, D_/32), 256>>>(wq, whi, wlo, D_, H_*HD_);
    gemm_hmma_kernel<<<dim3((H_*HD_)/128, MT/128), 256, GEMM_SMEM>>>(
        MT, H_*HD_, D_, ahi, alo, whi, wlo, gq);
    // k_self = hs @ wk
    wsplit_kernel<<<dim3((KV_*HD_)/32, D_/32), 256>>>(wk, whi, wlo, D_, KV_*HD_);
    gemm_hmma_kernel<<<dim3((KV_*HD_)/128, MT/128), 256, GEMM_SMEM>>>(
        MT, KV_*HD_, D_, ahi, alo, whi, wlo, gks);
    // v_self = hs @ wv
    wsplit_kernel<<<dim3((KV_*HD_)/32, D_/32), 256>>>(wv, whi, wlo, D_, KV_*HD_);
    gemm_hmma_kernel<<<dim3((KV_*HD_)/128, MT/128), 256, GEMM_SMEM>>>(
        MT, KV_*HD_, D_, ahi, alo, whi, wlo, gvs);
    // encoder activations (wv still resident in wt buffers)
    asplit_kernel<<<(B_*E_*D_)/1024, 256>>>(enc, ahi, alo, B_*E_*D_);
    gemm_hmma_kernel<<<dim3((KV_*HD_)/128, (B_*E_)/128), 256, GEMM_SMEM>>>(
        B_*E_, KV_*HD_, D_, ahi, alo, whi, wlo, gvc);
    // k_cross = enc @ wk
    wsplit_kernel<<<dim3((KV_*HD_)/32, D_/32), 256>>>(wk, whi, wlo, D_, KV_*HD_);
    gemm_hmma_kernel<<<dim3((KV_*HD_)/128, (B_*E_)/128), 256, GEMM_SMEM>>>(
        B_*E_, KV_*HD_, D_, ahi, alo, whi, wlo, gkc);

    // segments, norms, rope
    seg_kernel<<<B_, 1024>>>(pos);
    norm_rope_kernel<<<B_*S_*H_,  256>>>(gq,  qnw, cosp, sinp, H_,  1);
    norm_rope_kernel<<<B_*S_*KV_, 256>>>(gks, knw, cosp, sinp, KV_, 1);
    norm_rope_kernel<<<B_*E_*KV_, 256>>>(gkc, knw, cosp, sinp, KV_, 0);

    // attention
    int smem_bytes = 32 * HD_ * 2 * (int)sizeof(float);
    cudaFuncSetAttribute(attn_kernel, cudaFuncAttributeMaxDynamicSharedMemorySize, smem_bytes);
    attn_kernel<<<dim3(S_/32, H_, B_), 256, smem_bytes>>>(dmsk, emsk);

    // output projection: out = attn @ wo
    asplit_kernel<<<(MT*(H_*HD_))/1024, 256>>>(gat, ahi, alo, MT*H_*HD_);
    wsplit_kernel<<<dim3(D_/32, (H_*HD_)/32), 256>>>(wo, whi, wlo, H_*HD_, D_);
    gemm_hmma_kernel<<<dim3(D_/128, MT/128), 256, GEMM_SMEM>>>(
        MT, D_, H_*HD_, ahi, alo, whi, wlo, out);
}

// round 5
// speedup vs baseline: 1.7779x; 1.7779x over previous
#include <cuda_runtime.h>
#include <cuda_bf16.h>
#include <math.h>
#include <stdint.h>

#define B_ 2
#define S_ 1024
#define E_ 1024
#define D_ 2048
#define H_ 8
#define KV_ 4
#define HD_ 256
#define WINDOW_ 512
#define SOFTCAP_ 50.0f
#define SCALE_ 0.0625f

// ---------------- scratch ----------------
__device__ float g_q     [B_*S_*H_ *HD_];
__device__ float g_kself [B_*S_*KV_*HD_];
__device__ float g_vself [B_*S_*KV_*HD_];
__device__ float g_kcross[B_*E_*KV_*HD_];
__device__ float g_vcross[B_*E_*KV_*HD_];
__device__ float g_attn  [B_*S_*H_ *HD_];
__device__ __nv_bfloat16 g_act_hi[2048*2048];
__device__ __nv_bfloat16 g_act_lo[2048*2048];
__device__ __nv_bfloat16 g_wt_hi [2048*2048];
__device__ __nv_bfloat16 g_wt_lo [2048*2048];
__device__ __nv_bfloat16 g_Qhi [B_*S_*H_*HD_];
__device__ __nv_bfloat16 g_Qlo [B_*S_*H_*HD_];
__device__ __nv_bfloat16 g_Khi [B_*KV_*2048*HD_];
__device__ __nv_bfloat16 g_Klo [B_*KV_*2048*HD_];
__device__ __nv_bfloat16 g_Vthi[B_*KV_*HD_*2048];
__device__ __nv_bfloat16 g_Vtlo[B_*KV_*HD_*2048];
__device__ int2 g_kmeta[B_*2048];

// ---------------- PTX helpers ----------------
__device__ __forceinline__ uint32_t smem_u32(const void* p){
    uint32_t a;
    asm("{ .reg .u64 t; cvta.to.shared.u64 t, %1; cvt.u32.u64 %0, t; }" : "=r"(a) : "l"(p));
    return a;
}
__device__ __forceinline__ void cpa16(uint32_t s, const void* g){
    asm volatile("cp.async.cg.shared.global [%0], [%1], 16;" :: "r"(s), "l"(g) : "memory");
}
__device__ __forceinline__ void cp_commit(){
    asm volatile("cp.async.commit_group;" ::: "memory");
}
template<int N> __device__ __forceinline__ void cp_wait(){
    asm volatile("cp.async.wait_group %0;" :: "n"(N) : "memory");
}
#define MMA16816(d, a, b) \
    asm volatile("mma.sync.aligned.m16n8k16.row.col.f32.bf16.bf16.f32 " \
        "{%0,%1,%2,%3},{%4,%5,%6,%7},{%8,%9},{%0,%1,%2,%3};" \
        : "+f"((d)[0]), "+f"((d)[1]), "+f"((d)[2]), "+f"((d)[3]) \
        : "r"((a)[0]), "r"((a)[1]), "r"((a)[2]), "r"((a)[3]), \
          "r"((b)[0]), "r"((b)[1]))
__device__ __forceinline__ uint32_t packbf2(float lo, float hi){
    __nv_bfloat162 v = __floats2bfloat162_rn(lo, hi);
    return *reinterpret_cast<uint32_t*>(&v);
}

// ================== HMMA bf16x3 GEMM: BM128 x BN64, 3-stage ==================
#define LDROW 80
#define ABUF (128*LDROW)
#define BBUF (64*LDROW)
#define OFF_AH 0
#define OFF_AL (ABUF)
#define OFF_BH (2*ABUF)
#define OFF_BL (2*ABUF + BBUF)
#define STG_BYTES (2*ABUF + 2*BBUF)
#define GEMM_SMEM (3*STG_BYTES)

__global__ __launch_bounds__(256, 2) void gemm_hmma_kernel(
    int M, int N, int K,
    const __nv_bfloat16* __restrict__ Ahi, const __nv_bfloat16* __restrict__ Alo,
    const __nv_bfloat16* __restrict__ Bhi, const __nv_bfloat16* __restrict__ Blo,
    float* __restrict__ C)
{
    extern __shared__ char dsm[];
    const uint32_t sb = smem_u32(dsm);
    const int tid = threadIdx.x;
    const int lane = tid & 31, w = tid >> 5;
    const int g = lane >> 2, tg = lane & 3;
    const int wm = w & 3, wn = w >> 2;        // 4x2 warps, 32x32 warp tile
    const int bx = blockIdx.x, by = blockIdx.y;

    const __nv_bfloat16* gp0 = Ahi + (size_t)by * 128 * K;
    const __nv_bfloat16* gp1 = Alo + (size_t)by * 128 * K;
    const __nv_bfloat16* gp2 = Bhi + (size_t)bx * 64 * K;
    const __nv_bfloat16* gp3 = Blo + (size_t)bx * 64 * K;

    float acc[2][4][4];
    #pragma unroll
    for (int mt = 0; mt < 2; mt++)
        #pragma unroll
        for (int nt = 0; nt < 4; nt++)
            #pragma unroll
            for (int i = 0; i < 4; i++) acc[mt][nt][i] = 0.f;

    const int niter = K >> 5;

    auto load_stage = [&](int stage, int k0){
        uint32_t s0 = sb + stage * STG_BYTES;
        #pragma unroll
        for (int i = 0; i < 6; i++){
            int c = i * 256 + tid;
            if (c < 1024){
                int row = (c >> 2) & 127, ch = c & 3;
                const __nv_bfloat16* gp = (c < 512) ? gp0 : gp1;
                uint32_t off = (c < 512) ? OFF_AH : OFF_AL;
                cpa16(s0 + off + row * LDROW + ch * 16, gp + (size_t)row * K + k0 + ch * 8);
            } else {
                int c2 = c - 1024;
                int row = (c2 >> 2) & 63, ch = c2 & 3;
                const __nv_bfloat16* gp = (c2 < 256) ? gp2 : gp3;
                uint32_t off = (c2 < 256) ? OFF_BH : OFF_BL;
                cpa16(s0 + off + row * LDROW + ch * 16, gp + (size_t)row * K + k0 + ch * 8);
            }
        }
        cp_commit();
    };

    load_stage(0, 0);
    load_stage(1, 32);

    int st = 0, pf = 2;
    for (int it = 0; it < niter; it++){
        if (it + 1 < niter) cp_wait<1>(); else cp_wait<0>();
        __syncthreads();
        if (it + 2 < niter){
            load_stage(pf, (it + 2) * 32);
            if (++pf == 3) pf = 0;
        }
        const char* s = dsm + st * STG_BYTES;
        if (++st == 3) st = 0;

        #pragma unroll
        for (int ks = 0; ks < 2; ks++){
            const int colB = ks * 32 + tg * 4;
            uint32_t ah[2][4], al[2][4];
            #pragma unroll
            for (int mt = 0; mt < 2; mt++){
                const char* p = s + OFF_AH + (wm * 32 + mt * 16 + g) * LDROW + colB;
                ah[mt][0] = *(const uint32_t*)(p);
                ah[mt][1] = *(const uint32_t*)(p + 8 * LDROW);
                ah[mt][2] = *(const uint32_t*)(p + 16);
                ah[mt][3] = *(const uint32_t*)(p + 8 * LDROW + 16);
                const char* q = p + ABUF;
                al[mt][0] = *(const uint32_t*)(q);
                al[mt][1] = *(const uint32_t*)(q + 8 * LDROW);
                al[mt][2] = *(const uint32_t*)(q + 16);
                al[mt][3] = *(const uint32_t*)(q + 8 * LDROW + 16);
            }
            uint32_t bh[4][2], bl[4][2];
            #pragma unroll
            for (int nt = 0; nt < 4; nt++){
                const char* p = s + OFF_BH + (wn * 32 + nt * 8 + g) * LDROW + colB;
                bh[nt][0] = *(const uint32_t*)(p);
                bh[nt][1] = *(const uint32_t*)(p + 16);
                const char* q = p + BBUF;
                bl[nt][0] = *(const uint32_t*)(q);
                bl[nt][1] = *(const uint32_t*)(q + 16);
            }
            #pragma unroll
            for (int mt = 0; mt < 2; mt++)
                #pragma unroll
                for (int nt = 0; nt < 4; nt++){
                    MMA16816(acc[mt][nt], ah[mt], bh[nt]);
                    MMA16816(acc[mt][nt], ah[mt], bl[nt]);
                    MMA16816(acc[mt][nt], al[mt], bh[nt]);
                }
        }
    }

    #pragma unroll
    for (int mt = 0; mt < 2; mt++){
        int r = by * 128 + wm * 32 + mt * 16 + g;
        #pragma unroll
        for (int nt = 0; nt < 4; nt++){
            int c = bx * 64 + wn * 32 + nt * 8 + 2 * tg;
            *(float2*)(C + (size_t)r * N + c)       = make_float2(acc[mt][nt][0], acc[mt][nt][1]);
            *(float2*)(C + (size_t)(r + 8) * N + c) = make_float2(acc[mt][nt][2], acc[mt][nt][3]);
        }
    }
}

// ---------------- fp32 -> bf16 hi/lo split ----------------
__global__ __launch_bounds__(256) void asplit_kernel(
    const float* __restrict__ x, __nv_bfloat16* __restrict__ hi,
    __nv_bfloat16* __restrict__ lo, int n)
{
    int i = (blockIdx.x * 256 + threadIdx.x) * 4;
    if (i >= n) return;
    float4 v = *(const float4*)(x + i);
    float a[4] = {v.x, v.y, v.z, v.w};
    __nv_bfloat16 h[4], l[4];
    #pragma unroll
    for (int j = 0; j < 4; j++){
        h[j] = __float2bfloat16(a[j]);
        l[j] = __float2bfloat16(a[j] - __bfloat162float(h[j]));
    }
    *(__nv_bfloat162*)(hi + i)     = __nv_bfloat162(h[0], h[1]);
    *(__nv_bfloat162*)(hi + i + 2) = __nv_bfloat162(h[2], h[3]);
    *(__nv_bfloat162*)(lo + i)     = __nv_bfloat162(l[0], l[1]);
    *(__nv_bfloat162*)(lo + i + 2) = __nv_bfloat162(l[2], l[3]);
}

// ---------------- weight transpose + split ----------------
__global__ __launch_bounds__(256) void wsplit_kernel(
    const float* __restrict__ W, __nv_bfloat16* __restrict__ hi,
    __nv_bfloat16* __restrict__ lo, int K, int N)
{
    __shared__ float t[32][33];
    int n0 = blockIdx.x * 32, k0 = blockIdx.y * 32;
    int tx = threadIdx.x & 31, ty = threadIdx.x >> 5;
    #pragma unroll
    for (int r = 0; r < 32; r += 8)
        t[ty + r][tx] = W[(size_t)(k0 + ty + r) * N + n0 + tx];
    __syncthreads();
    #pragma unroll
    for (int r = 0; r < 32; r += 8){
        float v = t[tx][ty + r];
        __nv_bfloat16 h = __float2bfloat16(v);
        __nv_bfloat16 l = __float2bfloat16(v - __bfloat162float(h));
        size_t o = (size_t)(n0 + ty + r) * K + k0 + tx;
        hi[o] = h; lo[o] = l;
    }
}

// ---------------- seg scan + key metadata ----------------
__global__ __launch_bounds__(1024) void seg_meta_kernel(
    const int* __restrict__ pos, const int* __restrict__ dmask,
    const int* __restrict__ emask)
{
    __shared__ int sh[1024];
    int b = blockIdx.x, i = threadIdx.x;
    int p = pos[b*S_ + i];
    int flag = (i == 0) ? 1 : ((p <= pos[b*S_ + i - 1]) ? 1 : 0);
    sh[i] = flag;
    __syncthreads();
    #pragma unroll
    for (int off = 1; off < 1024; off <<= 1){
        int v = sh[i];
        int add = (i >= off) ? sh[i - off] : 0;
        __syncthreads();
        sh[i] = v + add;
        __syncthreads();
    }
    g_kmeta[b*2048 + i]        = make_int2(dmask[b*S_ + i], sh[i]);
    g_kmeta[b*2048 + 1024 + i] = make_int2(emask[b*E_ + i], 0);
}

// ---------------- fused RMS norm (+RoPE) ----------------
__global__ __launch_bounds__(256) void norm_rope_kernel(
    float* __restrict__ buf, const float* __restrict__ nw,
    const float* __restrict__ cs, const float* __restrict__ sn,
    int nheads, int do_rope)
{
    int blk = blockIdx.x;
    int h = blk % nheads;
    int t = blk / nheads;
    float* x = buf + ((size_t)t * nheads + h) * HD_;
    int d = threadIdx.x;
    float v = x[d];
    float ss = v * v;
    __shared__ float red[8];
    #pragma unroll
    for (int o = 16; o; o >>= 1) ss += __shfl_xor_sync(0xffffffffu, ss, o);
    if ((d & 31) == 0) red[d >> 5] = ss;
    __syncthreads();
    float tot = 0.f;
    #pragma unroll
    for (int i = 0; i < 8; i++) tot += red[i];
    float inv = rsqrtf(tot * (1.0f / HD_) + 1e-6f);
    float xn = v * inv * (1.0f + nw[d]);
    if (do_rope) {
        __shared__ float sx[HD_];
        sx[d] = xn;
        __syncthreads();
        float rot = (d < HD_/2) ? -sx[d + HD_/2] : sx[d - HD_/2];
        xn = xn * cs[(size_t)t * HD_ + d] + rot * sn[(size_t)t * HD_ + d];
    }
    x[d] = xn;
}

// ---------------- K combine self+cross -> [b,kv,j,d] bf16 split ----------------
__global__ __launch_bounds__(256) void kcombine_kernel()
{
    int i4 = (blockIdx.x * 256 + threadIdx.x) * 4;
    int d   = i4 & 255;
    int j   = (i4 >> 8) & 2047;
    int kvb = i4 >> 19;
    int kv = kvb & 3, b = kvb >> 2;
    const float* src = (j < 1024)
        ? (g_kself  + ((size_t)((b*1024 + j)        * 4 + kv)) * 256 + d)
        : (g_kcross + ((size_t)((b*1024 + j - 1024) * 4 + kv)) * 256 + d);
    float4 v = *(const float4*)src;
    float a[4] = {v.x, v.y, v.z, v.w};
    __nv_bfloat16 h[4], l[4];
    #pragma unroll
    for (int t = 0; t < 4; t++){
        h[t] = __float2bfloat16(a[t]);
        l[t] = __float2bfloat16(a[t] - __bfloat162float(h[t]));
    }
    *(__nv_bfloat162*)(g_Khi + i4)     = __nv_bfloat162(h[0], h[1]);
    *(__nv_bfloat162*)(g_Khi + i4 + 2) = __nv_bfloat162(h[2], h[3]);
    *(__nv_bfloat162*)(g_Klo + i4)     = __nv_bfloat162(l[0], l[1]);
    *(__nv_bfloat162*)(g_Klo + i4 + 2) = __nv_bfloat162(l[2], l[3]);
}

// ---------------- V transpose + split -> Vt[b,kv,d,j] bf16 ----------------
__global__ __launch_bounds__(256) void vtsplit_kernel()
{
    __shared__ float t[32][33];
    int bkv = blockIdx.z;
    int b = bkv >> 2, kv = bkv & 3;
    int jt = blockIdx.x * 32, dt = blockIdx.y * 32;
    int tx = threadIdx.x & 31, ty = threadIdx.x >> 5;
    const float* src = (jt < 1024) ? g_vself : g_vcross;
    int j0 = (jt < 1024) ? jt : jt - 1024;
    #pragma unroll
    for (int r = 0; r < 32; r += 8)
        t[ty + r][tx] = src[((size_t)((b*1024 + j0 + ty + r) * 4 + kv)) * 256 + dt + tx];
    __syncthreads();
    #pragma unroll
    for (int r = 0; r < 32; r += 8){
        float v = t[tx][ty + r];
        __nv_bfloat16 h = __float2bfloat16(v);
        __nv_bfloat16 l = __float2bfloat16(v - __bfloat162float(h));
        size_t o = ((size_t)((b*4 + kv) * 256 + dt + ty + r)) * 2048 + jt + tx;
        g_Vthi[o] = h; g_Vtlo[o] = l;
    }
}

// ================== HMMA flash attention ==================
// 128 threads (4 warps), 64 queries/CTA, 32-key tiles double-buffered.
#define QROW_B 528
#define QBUF  (64*QROW_B)
#define ST_KHI 0
#define ST_KLO 16896
#define ST_VHI 33792
#define ST_VLO 54272
#define ST_META 74752
#define ST_SIZE 75008
#define ATT_SMEM (2*QBUF + 2*ST_SIZE)
#define SMASK  (-1.0e4f)
#define MINIT  (-100.0f)

__global__ void __launch_bounds__(128, 1) attn2_kernel()
{
    extern __shared__ char sm[];
    const uint32_t sbase = smem_u32(sm);
    const int tid = threadIdx.x, lane = tid & 31, wm = tid >> 5;
    const int g = lane >> 2, tg = lane & 3;
    const int b = blockIdx.z, h = blockIdx.y, qb = blockIdx.x * 64;
    const int kv = h >> 1;

    const char* qhi_g = (const char*)g_Qhi + ((size_t)((b*1024 + qb)*8 + h)) * 512;
    const char* qlo_g = (const char*)g_Qlo + ((size_t)((b*1024 + qb)*8 + h)) * 512;
    const char* khi_g = (const char*)g_Khi + ((size_t)(b*4 + kv)) * 2048 * 512;
    const char* klo_g = (const char*)g_Klo + ((size_t)(b*4 + kv)) * 2048 * 512;
    const char* vhi_g = (const char*)g_Vthi + ((size_t)(b*4 + kv)) * 256 * 4096;
    const char* vlo_g = (const char*)g_Vtlo + ((size_t)(b*4 + kv)) * 256 * 4096;

    int first = qb - (WINDOW_ - 1);
    int t_lo = (first <= 0) ? 0 : (first >> 5);
    int nself = ((qb + 63) >> 5) - t_lo + 1;
    int ntiles = nself + E_ / 32;

    auto jbase_of = [&](int t){ return (t < nself) ? (t_lo + t) * 32 : 1024 + (t - nself) * 32; };

    auto load_tile = [&](int stg, int t){
        int jbase = jbase_of(t);
        uint32_t sb = sbase + 2*QBUF + stg * ST_SIZE;
        #pragma unroll
        for (int i = 0; i < 8; i++){
            int c = i * 128 + tid;          // 0..1023
            int j = c >> 5, ch = c & 31;
            cpa16(sb + ST_KHI + j * QROW_B + ch * 16, khi_g + (size_t)(jbase + j) * 512 + ch * 16);
            cpa16(sb + ST_KLO + j * QROW_B + ch * 16, klo_g + (size_t)(jbase + j) * 512 + ch * 16);
            int d = c >> 2, cv = c & 3;
            cpa16(sb + ST_VHI + d * 80 + cv * 16, vhi_g + (size_t)d * 4096 + jbase * 2 + cv * 16);
            cpa16(sb + ST_VLO + d * 80 + cv * 16, vlo_g + (size_t)d * 4096 + jbase * 2 + cv * 16);
        }
        if (tid < 16)
            cpa16(sb + ST_META + tid * 16,
                  (const char*)g_kmeta + ((size_t)b * 2048 + jbase) * 8 + tid * 16);
        cp_commit();
    };

    // Q tile (hi+lo) bundled into group 0 with tile 0
    #pragma unroll
    for (int i = 0; i < 16; i++){
        int c = i * 128 + tid;              // 0..2047
        int r = c >> 5, ch = c & 31;
        cpa16(sbase + r * QROW_B + ch * 16,        qhi_g + (size_t)r * 4096 + ch * 16);
        cpa16(sbase + QBUF + r * QROW_B + ch * 16, qlo_g + (size_t)r * 4096 + ch * 16);
    }
    load_tile(0, 0);
    load_tile(1, 1);

    const int qg0 = qb + wm * 16 + g;
    const int qseg0 = g_kmeta[b*2048 + qg0].y;
    const int qseg1 = g_kmeta[b*2048 + qg0 + 8].y;

    float out[32][4];
    #pragma unroll
    for (int nt = 0; nt < 32; nt++)
        #pragma unroll
        for (int i = 0; i < 4; i++) out[nt][i] = 0.f;
    float m0 = MINIT, m1 = MINIT, l0 = 0.f, l1 = 0.f;

    const char* qh = sm;
    const char* ql = sm + QBUF;
    const int arow = wm * 16 + g;

    for (int t = 0; t < ntiles; t++){
        int stg = t & 1;
        bool is_self = (t < nself);
        int jbase = jbase_of(t);
        if (t + 1 < ntiles) cp_wait<1>(); else cp_wait<0>();
        __syncthreads();

        const char* ks = sm + 2*QBUF + stg * ST_SIZE;
        const char* vh = ks + ST_VHI;
        const char* vl = ks + ST_VLO;
        const int2* meta = (const int2*)(ks + ST_META);

        // ---- QK^T bf16x3 ----
        float sf[4][4];
        #pragma unroll
        for (int nt = 0; nt < 4; nt++)
            #pragma unroll
            for (int i = 0; i < 4; i++) sf[nt][i] = 0.f;

        #pragma unroll
        for (int kc = 0; kc < 16; kc++){
            const int colB = kc * 32 + tg * 4;
            uint32_t ah[4], al[4];
            const char* p = qh + arow * QROW_B + colB;
            ah[0] = *(const uint32_t*)(p);
            ah[1] = *(const uint32_t*)(p + 8 * QROW_B);
            ah[2] = *(const uint32_t*)(p + 16);
            ah[3] = *(const uint32_t*)(p + 8 * QROW_B + 16);
            const char* q2 = ql + arow * QROW_B + colB;
            al[0] = *(const uint32_t*)(q2);
            al[1] = *(const uint32_t*)(q2 + 8 * QROW_B);
            al[2] = *(const uint32_t*)(q2 + 16);
            al[3] = *(const uint32_t*)(q2 + 8 * QROW_B + 16);
            #pragma unroll
            for (int nt = 0; nt < 4; nt++){
                const char* pk = ks + ST_KHI + (nt * 8 + g) * QROW_B + colB;
                uint32_t bh[2], bl[2];
                bh[0] = *(const uint32_t*)(pk);
                bh[1] = *(const uint32_t*)(pk + 16);
                const char* qk = ks + ST_KLO + (nt * 8 + g) * QROW_B + colB;
                bl[0] = *(const uint32_t*)(qk);
                bl[1] = *(const uint32_t*)(qk + 16);
                MMA16816(sf[nt], ah, bh);
                MMA16816(sf[nt], ah, bl);
                MMA16816(sf[nt], al, bh);
            }
        }

        // ---- scale + softcap + mask ----
        #pragma unroll
        for (int nt = 0; nt < 4; nt++){
            #pragma unroll
            for (int i = 0; i < 4; i++){
                int c = i & 1, half = i >> 1;
                int col = nt * 8 + 2 * tg + c;
                float sc = sf[nt][i] * SCALE_;
                float x2 = fabsf(sc) * (2.0f / SOFTCAP_);
                float e = __expf(-x2);
                float th = __fdividef(1.0f - e, 1.0f + e);
                sc = copysignf(SOFTCAP_ * th, sc);
                int2 mt = meta[col];
                bool ok = (mt.x != 0);
                if (is_self){
                    int j = jbase + col;
                    int qg = qg0 + (half << 3);
                    int qs = half ? qseg1 : qseg0;
                    ok = ok && (j <= qg) && (qg - j < WINDOW_) && (mt.y == qs);
                }
                sf[nt][i] = ok ? sc : SMASK;
            }
        }

        // ---- online softmax (rows g, g+8) ----
        float tm0 = m0, tm1 = m1;
        #pragma unroll
        for (int nt = 0; nt < 4; nt++){
            tm0 = fmaxf(tm0, fmaxf(sf[nt][0], sf[nt][1]));
            tm1 = fmaxf(tm1, fmaxf(sf[nt][2], sf[nt][3]));
        }
        tm0 = fmaxf(tm0, __shfl_xor_sync(0xffffffffu, tm0, 1));
        tm0 = fmaxf(tm0, __shfl_xor_sync(0xffffffffu, tm0, 2));
        tm1 = fmaxf(tm1, __shfl_xor_sync(0xffffffffu, tm1, 1));
        tm1 = fmaxf(tm1, __shfl_xor_sync(0xffffffffu, tm1, 2));
        float corr0 = __expf(m0 - tm0);
        float corr1 = __expf(m1 - tm1);
        m0 = tm0; m1 = tm1;
        float s0 = 0.f, s1 = 0.f;
        #pragma unroll
        for (int nt = 0; nt < 4; nt++){
            sf[nt][0] = __expf(sf[nt][0] - tm0);
            sf[nt][1] = __expf(sf[nt][1] - tm0);
            sf[nt][2] = __expf(sf[nt][2] - tm1);
            sf[nt][3] = __expf(sf[nt][3] - tm1);
            s0 += sf[nt][0] + sf[nt][1];
            s1 += sf[nt][2] + sf[nt][3];
        }
        s0 += __shfl_xor_sync(0xffffffffu, s0, 1);
        s0 += __shfl_xor_sync(0xffffffffu, s0, 2);
        s1 += __shfl_xor_sync(0xffffffffu, s1, 1);
        s1 += __shfl_xor_sync(0xffffffffu, s1, 2);
        l0 = l0 * corr0 + s0;
        l1 = l1 * corr1 + s1;

        #pragma unroll
        for (int nt = 0; nt < 32; nt++){
            out[nt][0] *= corr0; out[nt][1] *= corr0;
            out[nt][2] *= corr1; out[nt][3] *= corr1;
        }

        // ---- P·V bf16x3: P frags repacked from score frags ----
        #pragma unroll
        for (int kc2 = 0; kc2 < 2; kc2++){
            float* sA = sf[kc2 * 2];
            float* sB = sf[kc2 * 2 + 1];
            uint32_t ph[4], pl[4];
            float hA0 = __bfloat162float(__float2bfloat16(sA[0]));
            float hA1 = __bfloat162float(__float2bfloat16(sA[1]));
            float hA2 = __bfloat162float(__float2bfloat16(sA[2]));
            float hA3 = __bfloat162float(__float2bfloat16(sA[3]));
            float hB0 = __bfloat162float(__float2bfloat16(sB[0]));
            float hB1 = __bfloat162float(__float2bfloat16(sB[1]));
            float hB2 = __bfloat162float(__float2bfloat16(sB[2]));
            float hB3 = __bfloat162float(__float2bfloat16(sB[3]));
            ph[0] = packbf2(hA0, hA1);
            ph[1] = packbf2(hA2, hA3);
            ph[2] = packbf2(hB0, hB1);
            ph[3] = packbf2(hB2, hB3);
            pl[0] = packbf2(sA[0]-hA0, sA[1]-hA1);
            pl[1] = packbf2(sA[2]-hA2, sA[3]-hA3);
            pl[2] = packbf2(sB[0]-hB0, sB[1]-hB1);
            pl[3] = packbf2(sB[2]-hB2, sB[3]-hB3);
            const int vcolB = kc2 * 32 + tg * 4;
            #pragma unroll
            for (int nt = 0; nt < 32; nt++){
                const char* pv = vh + (nt * 8 + g) * 80 + vcolB;
                uint32_t bhv[2], blv[2];
                bhv[0] = *(const uint32_t*)(pv);
                bhv[1] = *(const uint32_t*)(pv + 16);
                const char* qv = vl + (nt * 8 + g) * 80 + vcolB;
                blv[0] = *(const uint32_t*)(qv);
                blv[1] = *(const uint32_t*)(qv + 16);
                MMA16816(out[nt], ph, bhv);
                MMA16816(out[nt], ph, blv);
                MMA16816(out[nt], pl, bhv);
            }
        }
        __syncthreads();
        if (t + 2 < ntiles) load_tile(stg, t + 2);
    }

    // ---- epilogue ----
    float inv0 = 1.0f / l0, inv1 = 1.0f / l1;
    float* o0 = g_attn + ((size_t)((b*1024 + qg0)*8 + h)) * 256;
    float* o1 = g_attn + ((size_t)((b*1024 + qg0 + 8)*8 + h)) * 256;
    #pragma unroll
    for (int nt = 0; nt < 32; nt++){
        int c = nt * 8 + 2 * tg;
        *(float2*)(o0 + c) = make_float2(out[nt][0] * inv0, out[nt][1] * inv0);
        *(float2*)(o1 + c) = make_float2(out[nt][2] * inv1, out[nt][3] * inv1);
    }
}

// ---------------- launch ----------------
extern "C" void kernel_launch(void* const* d_in, const int* in_sizes, int n_in,
                              void* d_out, int out_size)
{
    const float* hs   = (const float*)d_in[0];
    const float* enc  = (const float*)d_in[1];
    const float* cosp = (const float*)d_in[2];
    const float* sinp = (const float*)d_in[3];
    const float* wq   = (const float*)d_in[4];
    const float* wk   = (const float*)d_in[5];
    const float* wv   = (const float*)d_in[6];
    const float* wo   = (const float*)d_in[7];
    const float* qnw  = (const float*)d_in[8];
    const float* knw  = (const float*)d_in[9];
    const int*   dmsk = (const int*)d_in[10];
    const int*   emsk = (const int*)d_in[11];
    const int*   pos  = (const int*)d_in[12];
    float* out = (float*)d_out;

    float *gq, *gks, *gvs, *gkc, *gvc, *gat;
    __nv_bfloat16 *ahi, *alo, *whi, *wlo, *qhi, *qlo;
    cudaGetSymbolAddress((void**)&gq,  g_q);
    cudaGetSymbolAddress((void**)&gks, g_kself);
    cudaGetSymbolAddress((void**)&gvs, g_vself);
    cudaGetSymbolAddress((void**)&gkc, g_kcross);
    cudaGetSymbolAddress((void**)&gvc, g_vcross);
    cudaGetSymbolAddress((void**)&gat, g_attn);
    cudaGetSymbolAddress((void**)&ahi, g_act_hi);
    cudaGetSymbolAddress((void**)&alo, g_act_lo);
    cudaGetSymbolAddress((void**)&whi, g_wt_hi);
    cudaGetSymbolAddress((void**)&wlo, g_wt_lo);
    cudaGetSymbolAddress((void**)&qhi, g_Qhi);
    cudaGetSymbolAddress((void**)&qlo, g_Qlo);

    cudaFuncSetAttribute(gemm_hmma_kernel,
                         cudaFuncAttributeMaxDynamicSharedMemorySize, GEMM_SMEM);
    cudaFuncSetAttribute(attn2_kernel,
                         cudaFuncAttributeMaxDynamicSharedMemorySize, ATT_SMEM);

    const int MT = B_*S_;
    asplit_kernel<<<(MT*D_)/1024, 256>>>(hs, ahi, alo, MT*D_);
    wsplit_kernel<<<dim3((H_*HD_)/32, D_/32), 256>>>(wq, whi, wlo, D_, H_*HD_);
    gemm_hmma_kernel<<<dim3((H_*HD_)/64, MT/128), 256, GEMM_SMEM>>>(
        MT, H_*HD_, D_, ahi, alo, whi, wlo, gq);
    wsplit_kernel<<<dim3((KV_*HD_)/32, D_/32), 256>>>(wk, whi, wlo, D_, KV_*HD_);
    gemm_hmma_kernel<<<dim3((KV_*HD_)/64, MT/128), 256, GEMM_SMEM>>>(
        MT, KV_*HD_, D_, ahi, alo, whi, wlo, gks);
    wsplit_kernel<<<dim3((KV_*HD_)/32, D_/32), 256>>>(wv, whi, wlo, D_, KV_*HD_);
    gemm_hmma_kernel<<<dim3((KV_*HD_)/64, MT/128), 256, GEMM_SMEM>>>(
        MT, KV_*HD_, D_, ahi, alo, whi, wlo, gvs);
    asplit_kernel<<<(B_*E_*D_)/1024, 256>>>(enc, ahi, alo, B_*E_*D_);
    gemm_hmma_kernel<<<dim3((KV_*HD_)/64, (B_*E_)/128), 256, GEMM_SMEM>>>(
        B_*E_, KV_*HD_, D_, ahi, alo, whi, wlo, gvc);
    wsplit_kernel<<<dim3((KV_*HD_)/32, D_/32), 256>>>(wk, whi, wlo, D_, KV_*HD_);
    gemm_hmma_kernel<<<dim3((KV_*HD_)/64, (B_*E_)/128), 256, GEMM_SMEM>>>(
        B_*E_, KV_*HD_, D_, ahi, alo, whi, wlo, gkc);

    seg_meta_kernel<<<B_, 1024>>>(pos, dmsk, emsk);
    norm_rope_kernel<<<B_*S_*H_,  256>>>(gq,  qnw, cosp, sinp, H_,  1);
    norm_rope_kernel<<<B_*S_*KV_, 256>>>(gks, knw, cosp, sinp, KV_, 1);
    norm_rope_kernel<<<B_*E_*KV_, 256>>>(gkc, knw, cosp, sinp, KV_, 0);

    // attention operand prep
    asplit_kernel<<<(MT*H_*HD_)/1024, 256>>>(gq, qhi, qlo, MT*H_*HD_);
    kcombine_kernel<<<(B_*KV_*2048*HD_)/1024, 256>>>();
    vtsplit_kernel<<<dim3(64, 8, B_*KV_), 256>>>();

    attn2_kernel<<<dim3(S_/64, H_, B_), 128, ATT_SMEM>>>();

    asplit_kernel<<<(MT*(H_*HD_))/1024, 256>>>(gat, ahi, alo, MT*H_*HD_);
    wsplit_kernel<<<dim3(D_/32, (H_*HD_)/32), 256>>>(wo, whi, wlo, H_*HD_, D_);
    gemm_hmma_kernel<<<dim3(D_/64, MT/128), 256, GEMM_SMEM>>>(
        MT, D_, H_*HD_, ahi, alo, whi, wlo, out);
}

// round 6
// speedup vs baseline: 2.0615x; 1.1595x over previous
#include <cuda_runtime.h>
#include <cuda_bf16.h>
#include <math.h>
#include <stdint.h>

#define B_ 2
#define S_ 1024
#define E_ 1024
#define D_ 2048
#define H_ 8
#define KV_ 4
#define HD_ 256
#define WINDOW_ 512
#define SOFTCAP_ 50.0f
#define SCALE_ 0.0625f

// ---------------- scratch ----------------
__device__ float g_q    [2048*2048];          // q projection out [t, h*256+d]
__device__ float g_kvout[4096*2048];          // [row: 0-2047 dec,2048-4095 enc][k|v]
__device__ __nv_bfloat16 g_act_hi[4096*2048]; // activations / attn-out splits
__device__ __nv_bfloat16 g_act_lo[4096*2048];
__device__ __nv_bfloat16 g_wt_hi [2048*2048]; // transposed weight splits [N,K]
__device__ __nv_bfloat16 g_wt_lo [2048*2048];
__device__ __nv_bfloat16 g_Qhi [B_*S_*H_*HD_];
__device__ __nv_bfloat16 g_Qlo [B_*S_*H_*HD_];
__device__ __nv_bfloat16 g_Khi [B_*KV_*2048*HD_];
__device__ __nv_bfloat16 g_Klo [B_*KV_*2048*HD_];
__device__ __nv_bfloat16 g_Vthi[B_*KV_*HD_*2048];
__device__ __nv_bfloat16 g_Vtlo[B_*KV_*HD_*2048];
__device__ int2 g_kmeta[B_*2048];

// ---------------- PTX helpers ----------------
__device__ __forceinline__ uint32_t smem_u32(const void* p){
    uint32_t a;
    asm("{ .reg .u64 t; cvta.to.shared.u64 t, %1; cvt.u32.u64 %0, t; }" : "=r"(a) : "l"(p));
    return a;
}
__device__ __forceinline__ void cpa16(uint32_t s, const void* g){
    asm volatile("cp.async.cg.shared.global [%0], [%1], 16;" :: "r"(s), "l"(g) : "memory");
}
__device__ __forceinline__ void cp_commit(){
    asm volatile("cp.async.commit_group;" ::: "memory");
}
template<int N> __device__ __forceinline__ void cp_wait(){
    asm volatile("cp.async.wait_group %0;" :: "n"(N) : "memory");
}
#define MMA16816(d, a, b) \
    asm volatile("mma.sync.aligned.m16n8k16.row.col.f32.bf16.bf16.f32 " \
        "{%0,%1,%2,%3},{%4,%5,%6,%7},{%8,%9},{%0,%1,%2,%3};" \
        : "+f"((d)[0]), "+f"((d)[1]), "+f"((d)[2]), "+f"((d)[3]) \
        : "r"((a)[0]), "r"((a)[1]), "r"((a)[2]), "r"((a)[3]), \
          "r"((b)[0]), "r"((b)[1]))
__device__ __forceinline__ uint32_t packbf2(float lo, float hi){
    __nv_bfloat162 v = __floats2bfloat162_rn(lo, hi);
    return *reinterpret_cast<uint32_t*>(&v);
}

// ================== HMMA bf16x3 GEMM: BM128 x BN128, 2-stage ==================
#define LDROW 80
#define BUFB (128*LDROW)           /* 10240 */
#define STG_BYTES (4*BUFB)         /* 40960: AH AL BH BL */
#define GEMM_SMEM (2*STG_BYTES)    /* 81920 */

__global__ __launch_bounds__(256, 2) void gemm_hmma_kernel(
    int M, int N, int K,
    const __nv_bfloat16* __restrict__ Ahi, const __nv_bfloat16* __restrict__ Alo,
    const __nv_bfloat16* __restrict__ Bhi, const __nv_bfloat16* __restrict__ Blo,
    float* __restrict__ C)
{
    extern __shared__ char dsm[];
    const uint32_t sb = smem_u32(dsm);
    const int tid = threadIdx.x;
    const int lane = tid & 31, w = tid >> 5;
    const int g = lane >> 2, tg = lane & 3;
    const int wm = w & 3, wn = w >> 2;        // 4x2 warps, warp tile 32x64
    const int bx = blockIdx.x, by = blockIdx.y;

    const __nv_bfloat16* gp0 = Ahi + (size_t)by * 128 * K;
    const __nv_bfloat16* gp1 = Alo + (size_t)by * 128 * K;
    const __nv_bfloat16* gp2 = Bhi + (size_t)bx * 128 * K;
    const __nv_bfloat16* gp3 = Blo + (size_t)bx * 128 * K;

    float acc[2][8][4];
    #pragma unroll
    for (int mt = 0; mt < 2; mt++)
        #pragma unroll
        for (int nt = 0; nt < 8; nt++)
            #pragma unroll
            for (int i = 0; i < 4; i++) acc[mt][nt][i] = 0.f;

    const int niter = K >> 5;   // BK=32

    auto load_stage = [&](int stage, int k0){
        #pragma unroll
        for (int i = 0; i < 8; i++){
            int c = i * 256 + tid;
            int r = (c >> 2) & 127;
            int ch = c & 3;
            uint32_t saddr = sb + stage * STG_BYTES + (c >> 9) * BUFB
                           + r * LDROW + ch * 16;
            const __nv_bfloat16* gp = (i < 2) ? gp0 : (i < 4) ? gp1 : (i < 6) ? gp2 : gp3;
            cpa16(saddr, gp + (size_t)r * K + k0 + ch * 8);
        }
        cp_commit();
    };

    load_stage(0, 0);
    load_stage(1, 32);

    for (int it = 0; it < niter; it++){
        if (it + 1 < niter) cp_wait<1>(); else cp_wait<0>();
        __syncthreads();
        const char* st = dsm + (it & 1) * STG_BYTES;

        #pragma unroll
        for (int ks = 0; ks < 32; ks += 16){
            const int acolB = (ks + 2 * tg) * 2;
            uint32_t ah[2][4], al[2][4];
            #pragma unroll
            for (int mt = 0; mt < 2; mt++){
                const char* p = st + (wm * 32 + mt * 16 + g) * LDROW + acolB;
                ah[mt][0] = *(const uint32_t*)(p);
                ah[mt][2] = *(const uint32_t*)(p + 16);
                ah[mt][1] = *(const uint32_t*)(p + 8 * LDROW);
                ah[mt][3] = *(const uint32_t*)(p + 8 * LDROW + 16);
                const char* q = p + BUFB;
                al[mt][0] = *(const uint32_t*)(q);
                al[mt][2] = *(const uint32_t*)(q + 16);
                al[mt][1] = *(const uint32_t*)(q + 8 * LDROW);
                al[mt][3] = *(const uint32_t*)(q + 8 * LDROW + 16);
            }
            uint32_t bh[8][2], bl[8][2];
            #pragma unroll
            for (int nt = 0; nt < 8; nt++){
                const char* p = st + 2 * BUFB + (wn * 64 + nt * 8 + g) * LDROW + acolB;
                bh[nt][0] = *(const uint32_t*)(p);
                bh[nt][1] = *(const uint32_t*)(p + 16);
                const char* q = p + BUFB;
                bl[nt][0] = *(const uint32_t*)(q);
                bl[nt][1] = *(const uint32_t*)(q + 16);
            }
            #pragma unroll
            for (int mt = 0; mt < 2; mt++)
                #pragma unroll
                for (int nt = 0; nt < 8; nt++){
                    MMA16816(acc[mt][nt], ah[mt], bh[nt]);
                    MMA16816(acc[mt][nt], ah[mt], bl[nt]);
                    MMA16816(acc[mt][nt], al[mt], bh[nt]);
                }
        }
        __syncthreads();
        if (it + 2 < niter) load_stage(it & 1, (it + 2) * 32);
    }

    #pragma unroll
    for (int mt = 0; mt < 2; mt++){
        int r = by * 128 + wm * 32 + mt * 16 + g;
        #pragma unroll
        for (int nt = 0; nt < 8; nt++){
            int c = bx * 128 + wn * 64 + nt * 8 + 2 * tg;
            *(float2*)(C + (size_t)r * N + c)       = make_float2(acc[mt][nt][0], acc[mt][nt][1]);
            *(float2*)(C + (size_t)(r + 8) * N + c) = make_float2(acc[mt][nt][2], acc[mt][nt][3]);
        }
    }
}

// ---------------- fp32 -> bf16 hi/lo split ----------------
__global__ __launch_bounds__(256) void asplit_kernel(
    const float* __restrict__ x, __nv_bfloat16* __restrict__ hi,
    __nv_bfloat16* __restrict__ lo, int n)
{
    int i = (blockIdx.x * 256 + threadIdx.x) * 4;
    if (i >= n) return;
    float4 v = *(const float4*)(x + i);
    float a[4] = {v.x, v.y, v.z, v.w};
    __nv_bfloat16 h[4], l[4];
    #pragma unroll
    for (int j = 0; j < 4; j++){
        h[j] = __float2bfloat16(a[j]);
        l[j] = __float2bfloat16(a[j] - __bfloat162float(h[j]));
    }
    *(__nv_bfloat162*)(hi + i)     = __nv_bfloat162(h[0], h[1]);
    *(__nv_bfloat162*)(hi + i + 2) = __nv_bfloat162(h[2], h[3]);
    *(__nv_bfloat162*)(lo + i)     = __nv_bfloat162(l[0], l[1]);
    *(__nv_bfloat162*)(lo + i + 2) = __nv_bfloat162(l[2], l[3]);
}

// ---------------- weight transpose + split: W[K,N] -> Wt[N,K] ----------------
__global__ __launch_bounds__(256) void wsplit_kernel(
    const float* __restrict__ W, __nv_bfloat16* __restrict__ hi,
    __nv_bfloat16* __restrict__ lo, int K, int N)
{
    __shared__ float t[32][33];
    int n0 = blockIdx.x * 32, k0 = blockIdx.y * 32;
    int tx = threadIdx.x & 31, ty = threadIdx.x >> 5;
    #pragma unroll
    for (int r = 0; r < 32; r += 8)
        t[ty + r][tx] = W[(size_t)(k0 + ty + r) * N + n0 + tx];
    __syncthreads();
    #pragma unroll
    for (int r = 0; r < 32; r += 8){
        float v = t[tx][ty + r];
        __nv_bfloat16 h = __float2bfloat16(v);
        __nv_bfloat16 l = __float2bfloat16(v - __bfloat162float(h));
        size_t o = (size_t)(n0 + ty + r) * K + k0 + tx;
        hi[o] = h; lo[o] = l;
    }
}

// ---------------- seg scan + key metadata ----------------
__global__ __launch_bounds__(1024) void seg_meta_kernel(
    const int* __restrict__ pos, const int* __restrict__ dmask,
    const int* __restrict__ emask)
{
    __shared__ int sh[1024];
    int b = blockIdx.x, i = threadIdx.x;
    int p = pos[b*S_ + i];
    int flag = (i == 0) ? 1 : ((p <= pos[b*S_ + i - 1]) ? 1 : 0);
    sh[i] = flag;
    __syncthreads();
    #pragma unroll
    for (int off = 1; off < 1024; off <<= 1){
        int v = sh[i];
        int add = (i >= off) ? sh[i - off] : 0;
        __syncthreads();
        sh[i] = v + add;
        __syncthreads();
    }
    g_kmeta[b*2048 + i]        = make_int2(dmask[b*S_ + i], sh[i]);
    g_kmeta[b*2048 + 1024 + i] = make_int2(emask[b*E_ + i], 0);
}

// ---------------- Q: RMS norm + RoPE -> bf16 split [t,h,d] ----------------
__global__ __launch_bounds__(256) void norm_q_kernel(
    const float* __restrict__ nw, const float* __restrict__ cs,
    const float* __restrict__ sn)
{
    int blk = blockIdx.x;            // t*8 + h
    int t = blk >> 3;
    const float* x = g_q + (size_t)blk * 256;
    int d = threadIdx.x;
    float v = x[d];
    float ss = v * v;
    __shared__ float red[8];
    __shared__ float sx[256];
    #pragma unroll
    for (int o = 16; o; o >>= 1) ss += __shfl_xor_sync(0xffffffffu, ss, o);
    if ((d & 31) == 0) red[d >> 5] = ss;
    __syncthreads();
    float tot = 0.f;
    #pragma unroll
    for (int i = 0; i < 8; i++) tot += red[i];
    float inv = rsqrtf(tot * (1.0f / 256.0f) + 1e-6f);
    float xn = v * inv * (1.0f + nw[d]);
    sx[d] = xn;
    __syncthreads();
    float rot = (d < 128) ? -sx[d + 128] : sx[d - 128];
    xn = xn * cs[(size_t)t * 256 + d] + rot * sn[(size_t)t * 256 + d];
    __nv_bfloat16 h = __float2bfloat16(xn);
    g_Qhi[(size_t)blk * 256 + d] = h;
    g_Qlo[(size_t)blk * 256 + d] = __float2bfloat16(xn - __bfloat162float(h));
}

// ---------------- K: RMS norm (+RoPE if self) -> bf16 split [b,kv,j,d] -------
__global__ __launch_bounds__(256) void norm_k_kernel(
    const float* __restrict__ nw, const float* __restrict__ cs,
    const float* __restrict__ sn)
{
    int blk = blockIdx.x;            // row*4 + kv, row in 0..4095
    int kv = blk & 3;
    int row = blk >> 2;
    bool is_self = row < 2048;
    int d = threadIdx.x;
    float v = g_kvout[(size_t)row * 2048 + kv * 256 + d];
    float ss = v * v;
    __shared__ float red[8];
    __shared__ float sx[256];
    #pragma unroll
    for (int o = 16; o; o >>= 1) ss += __shfl_xor_sync(0xffffffffu, ss, o);
    if ((d & 31) == 0) red[d >> 5] = ss;
    __syncthreads();
    float tot = 0.f;
    #pragma unroll
    for (int i = 0; i < 8; i++) tot += red[i];
    float inv = rsqrtf(tot * (1.0f / 256.0f) + 1e-6f);
    float xn = v * inv * (1.0f + nw[d]);
    if (is_self){
        sx[d] = xn;
        __syncthreads();
        float rot = (d < 128) ? -sx[d + 128] : sx[d - 128];
        xn = xn * cs[(size_t)row * 256 + d] + rot * sn[(size_t)row * 256 + d];
    }
    int b = is_self ? (row >> 10) : ((row >> 10) - 2);
    int j = is_self ? (row & 1023) : (1024 + (row & 1023));
    size_t o = ((size_t)((b*4 + kv) * 2048 + j)) * 256 + d;
    __nv_bfloat16 h = __float2bfloat16(xn);
    g_Khi[o] = h;
    g_Klo[o] = __float2bfloat16(xn - __bfloat162float(h));
}

// ---------------- V transpose + split from kvout -> Vt[b,kv,d,j] ------------
__global__ __launch_bounds__(256) void vtsplit_kernel()
{
    __shared__ float t[32][33];
    int bkv = blockIdx.z;
    int b = bkv >> 2, kv = bkv & 3;
    int jt = blockIdx.x * 32, dt = blockIdx.y * 32;
    int tx = threadIdx.x & 31, ty = threadIdx.x >> 5;
    int rowbase = (jt < 1024) ? (b*1024 + jt) : (2048 + b*1024 + jt - 1024);
    #pragma unroll
    for (int r = 0; r < 32; r += 8)
        t[ty + r][tx] = g_kvout[(size_t)(rowbase + ty + r) * 2048 + 1024 + kv*256 + dt + tx];
    __syncthreads();
    #pragma unroll
    for (int r = 0; r < 32; r += 8){
        float v = t[tx][ty + r];
        __nv_bfloat16 h = __float2bfloat16(v);
        __nv_bfloat16 l = __float2bfloat16(v - __bfloat162float(h));
        size_t o = ((size_t)((b*4 + kv) * 256 + dt + ty + r)) * 2048 + jt + tx;
        g_Vthi[o] = h; g_Vtlo[o] = l;
    }
}

// ================== HMMA flash attention ==================
#define QROW_B 528
#define QBUF  (64*QROW_B)
#define ST_KHI 0
#define ST_KLO 16896
#define ST_VHI 33792
#define ST_VLO 54272
#define ST_META 74752
#define ST_SIZE 75008
#define ATT_SMEM (2*QBUF + 2*ST_SIZE)
#define SMASK  (-1.0e4f)
#define MINIT  (-100.0f)

__global__ void __launch_bounds__(128, 1) attn2_kernel()
{
    extern __shared__ char sm[];
    const uint32_t sbase = smem_u32(sm);
    const int tid = threadIdx.x, lane = tid & 31, wm = tid >> 5;
    const int g = lane >> 2, tg = lane & 3;
    const int b = blockIdx.z, h = blockIdx.y, qb = blockIdx.x * 64;
    const int kv = h >> 1;

    const char* qhi_g = (const char*)g_Qhi + ((size_t)((b*1024 + qb)*8 + h)) * 512;
    const char* qlo_g = (const char*)g_Qlo + ((size_t)((b*1024 + qb)*8 + h)) * 512;
    const char* khi_g = (const char*)g_Khi + ((size_t)(b*4 + kv)) * 2048 * 512;
    const char* klo_g = (const char*)g_Klo + ((size_t)(b*4 + kv)) * 2048 * 512;
    const char* vhi_g = (const char*)g_Vthi + ((size_t)(b*4 + kv)) * 256 * 4096;
    const char* vlo_g = (const char*)g_Vtlo + ((size_t)(b*4 + kv)) * 256 * 4096;

    int first = qb - (WINDOW_ - 1);
    int t_lo = (first <= 0) ? 0 : (first >> 5);
    int nself = ((qb + 63) >> 5) - t_lo + 1;
    int ntiles = nself + E_ / 32;

    auto jbase_of = [&](int t){ return (t < nself) ? (t_lo + t) * 32 : 1024 + (t - nself) * 32; };

    auto load_tile = [&](int stg, int t){
        int jbase = jbase_of(t);
        uint32_t sb = sbase + 2*QBUF + stg * ST_SIZE;
        #pragma unroll
        for (int i = 0; i < 8; i++){
            int c = i * 128 + tid;
            int j = c >> 5, ch = c & 31;
            cpa16(sb + ST_KHI + j * QROW_B + ch * 16, khi_g + (size_t)(jbase + j) * 512 + ch * 16);
            cpa16(sb + ST_KLO + j * QROW_B + ch * 16, klo_g + (size_t)(jbase + j) * 512 + ch * 16);
            int d = c >> 2, cvx = c & 3;
            cpa16(sb + ST_VHI + d * 80 + cvx * 16, vhi_g + (size_t)d * 4096 + jbase * 2 + cvx * 16);
            cpa16(sb + ST_VLO + d * 80 + cvx * 16, vlo_g + (size_t)d * 4096 + jbase * 2 + cvx * 16);
        }
        if (tid < 16)
            cpa16(sb + ST_META + tid * 16,
                  (const char*)g_kmeta + ((size_t)b * 2048 + jbase) * 8 + tid * 16);
        cp_commit();
    };

    #pragma unroll
    for (int i = 0; i < 16; i++){
        int c = i * 128 + tid;
        int r = c >> 5, ch = c & 31;
        cpa16(sbase + r * QROW_B + ch * 16,        qhi_g + (size_t)r * 4096 + ch * 16);
        cpa16(sbase + QBUF + r * QROW_B + ch * 16, qlo_g + (size_t)r * 4096 + ch * 16);
    }
    load_tile(0, 0);
    load_tile(1, 1);

    const int qg0 = qb + wm * 16 + g;
    const int qseg0 = g_kmeta[b*2048 + qg0].y;
    const int qseg1 = g_kmeta[b*2048 + qg0 + 8].y;

    float out[32][4];
    #pragma unroll
    for (int nt = 0; nt < 32; nt++)
        #pragma unroll
        for (int i = 0; i < 4; i++) out[nt][i] = 0.f;
    float m0 = MINIT, m1 = MINIT, l0 = 0.f, l1 = 0.f;

    const char* qh = sm;
    const char* ql = sm + QBUF;
    const int arow = wm * 16 + g;

    for (int t = 0; t < ntiles; t++){
        int stg = t & 1;
        bool is_self = (t < nself);
        int jbase = jbase_of(t);
        if (t + 1 < ntiles) cp_wait<1>(); else cp_wait<0>();
        __syncthreads();

        const char* ks = sm + 2*QBUF + stg * ST_SIZE;
        const char* vh = ks + ST_VHI;
        const char* vl = ks + ST_VLO;
        const int2* meta = (const int2*)(ks + ST_META);

        float sf[4][4];
        #pragma unroll
        for (int nt = 0; nt < 4; nt++)
            #pragma unroll
            for (int i = 0; i < 4; i++) sf[nt][i] = 0.f;

        #pragma unroll
        for (int kc = 0; kc < 16; kc++){
            const int colB = kc * 32 + tg * 4;
            uint32_t ah[4], al[4];
            const char* p = qh + arow * QROW_B + colB;
            ah[0] = *(const uint32_t*)(p);
            ah[1] = *(const uint32_t*)(p + 8 * QROW_B);
            ah[2] = *(const uint32_t*)(p + 16);
            ah[3] = *(const uint32_t*)(p + 8 * QROW_B + 16);
            const char* q2 = ql + arow * QROW_B + colB;
            al[0] = *(const uint32_t*)(q2);
            al[1] = *(const uint32_t*)(q2 + 8 * QROW_B);
            al[2] = *(const uint32_t*)(q2 + 16);
            al[3] = *(const uint32_t*)(q2 + 8 * QROW_B + 16);
            #pragma unroll
            for (int nt = 0; nt < 4; nt++){
                const char* pk = ks + ST_KHI + (nt * 8 + g) * QROW_B + colB;
                uint32_t bh[2], bl[2];
                bh[0] = *(const uint32_t*)(pk);
                bh[1] = *(const uint32_t*)(pk + 16);
                const char* qk = ks + ST_KLO + (nt * 8 + g) * QROW_B + colB;
                bl[0] = *(const uint32_t*)(qk);
                bl[1] = *(const uint32_t*)(qk + 16);
                MMA16816(sf[nt], ah, bh);
                MMA16816(sf[nt], ah, bl);
                MMA16816(sf[nt], al, bh);
            }
        }

        #pragma unroll
        for (int nt = 0; nt < 4; nt++){
            #pragma unroll
            for (int i = 0; i < 4; i++){
                int c = i & 1, half = i >> 1;
                int col = nt * 8 + 2 * tg + c;
                float sc = sf[nt][i] * SCALE_;
                float x2 = fabsf(sc) * (2.0f / SOFTCAP_);
                float e = __expf(-x2);
                float th = __fdividef(1.0f - e, 1.0f + e);
                sc = copysignf(SOFTCAP_ * th, sc);
                int2 mt = meta[col];
                bool ok = (mt.x != 0);
                if (is_self){
                    int j = jbase + col;
                    int qg = qg0 + (half << 3);
                    int qs = half ? qseg1 : qseg0;
                    ok = ok && (j <= qg) && (qg - j < WINDOW_) && (mt.y == qs);
                }
                sf[nt][i] = ok ? sc : SMASK;
            }
        }

        float tm0 = m0, tm1 = m1;
        #pragma unroll
        for (int nt = 0; nt < 4; nt++){
            tm0 = fmaxf(tm0, fmaxf(sf[nt][0], sf[nt][1]));
            tm1 = fmaxf(tm1, fmaxf(sf[nt][2], sf[nt][3]));
        }
        tm0 = fmaxf(tm0, __shfl_xor_sync(0xffffffffu, tm0, 1));
        tm0 = fmaxf(tm0, __shfl_xor_sync(0xffffffffu, tm0, 2));
        tm1 = fmaxf(tm1, __shfl_xor_sync(0xffffffffu, tm1, 1));
        tm1 = fmaxf(tm1, __shfl_xor_sync(0xffffffffu, tm1, 2));
        float corr0 = __expf(m0 - tm0);
        float corr1 = __expf(m1 - tm1);
        m0 = tm0; m1 = tm1;
        float s0 = 0.f, s1 = 0.f;
        #pragma unroll
        for (int nt = 0; nt < 4; nt++){
            sf[nt][0] = __expf(sf[nt][0] - tm0);
            sf[nt][1] = __expf(sf[nt][1] - tm0);
            sf[nt][2] = __expf(sf[nt][2] - tm1);
            sf[nt][3] = __expf(sf[nt][3] - tm1);
            s0 += sf[nt][0] + sf[nt][1];
            s1 += sf[nt][2] + sf[nt][3];
        }
        s0 += __shfl_xor_sync(0xffffffffu, s0, 1);
        s0 += __shfl_xor_sync(0xffffffffu, s0, 2);
        s1 += __shfl_xor_sync(0xffffffffu, s1, 1);
        s1 += __shfl_xor_sync(0xffffffffu, s1, 2);
        l0 = l0 * corr0 + s0;
        l1 = l1 * corr1 + s1;

        #pragma unroll
        for (int nt = 0; nt < 32; nt++){
            out[nt][0] *= corr0; out[nt][1] *= corr0;
            out[nt][2] *= corr1; out[nt][3] *= corr1;
        }

        #pragma unroll
        for (int kc2 = 0; kc2 < 2; kc2++){
            float* sA = sf[kc2 * 2];
            float* sB = sf[kc2 * 2 + 1];
            uint32_t ph[4], pl[4];
            float hA0 = __bfloat162float(__float2bfloat16(sA[0]));
            float hA1 = __bfloat162float(__float2bfloat16(sA[1]));
            float hA2 = __bfloat162float(__float2bfloat16(sA[2]));
            float hA3 = __bfloat162float(__float2bfloat16(sA[3]));
            float hB0 = __bfloat162float(__float2bfloat16(sB[0]));
            float hB1 = __bfloat162float(__float2bfloat16(sB[1]));
            float hB2 = __bfloat162float(__float2bfloat16(sB[2]));
            float hB3 = __bfloat162float(__float2bfloat16(sB[3]));
            ph[0] = packbf2(hA0, hA1);
            ph[1] = packbf2(hA2, hA3);
            ph[2] = packbf2(hB0, hB1);
            ph[3] = packbf2(hB2, hB3);
            pl[0] = packbf2(sA[0]-hA0, sA[1]-hA1);
            pl[1] = packbf2(sA[2]-hA2, sA[3]-hA3);
            pl[2] = packbf2(sB[0]-hB0, sB[1]-hB1);
            pl[3] = packbf2(sB[2]-hB2, sB[3]-hB3);
            const int vcolB = kc2 * 32 + tg * 4;
            #pragma unroll
            for (int nt = 0; nt < 32; nt++){
                const char* pv = vh + (nt * 8 + g) * 80 + vcolB;
                uint32_t bhv[2], blv[2];
                bhv[0] = *(const uint32_t*)(pv);
                bhv[1] = *(const uint32_t*)(pv + 16);
                const char* qv = vl + (nt * 8 + g) * 80 + vcolB;
                blv[0] = *(const uint32_t*)(qv);
                blv[1] = *(const uint32_t*)(qv + 16);
                MMA16816(out[nt], ph, bhv);
                MMA16816(out[nt], ph, blv);
                MMA16816(out[nt], pl, bhv);
            }
        }
        __syncthreads();
        if (t + 2 < ntiles) load_tile(stg, t + 2);
    }

    // epilogue: write bf16 split directly into act buffers (row t, col h*256+c)
    float inv0 = 1.0f / l0, inv1 = 1.0f / l1;
    size_t r0 = (size_t)(b*1024 + qg0) * 2048 + h * 256;
    size_t r1 = (size_t)(b*1024 + qg0 + 8) * 2048 + h * 256;
    #pragma unroll
    for (int nt = 0; nt < 32; nt++){
        int c = nt * 8 + 2 * tg;
        float v0 = out[nt][0] * inv0, v1 = out[nt][1] * inv0;
        float v2 = out[nt][2] * inv1, v3 = out[nt][3] * inv1;
        float h0 = __bfloat162float(__float2bfloat16(v0));
        float h1 = __bfloat162float(__float2bfloat16(v1));
        float h2 = __bfloat162float(__float2bfloat16(v2));
        float h3 = __bfloat162float(__float2bfloat16(v3));
        *(uint32_t*)((char*)g_act_hi + (r0 + c) * 2) = packbf2(h0, h1);
        *(uint32_t*)((char*)g_act_lo + (r0 + c) * 2) = packbf2(v0 - h0, v1 - h1);
        *(uint32_t*)((char*)g_act_hi + (r1 + c) * 2) = packbf2(h2, h3);
        *(uint32_t*)((char*)g_act_lo + (r1 + c) * 2) = packbf2(v2 - h2, v3 - h3);
    }
}

// ---------------- launch ----------------
extern "C" void kernel_launch(void* const* d_in, const int* in_sizes, int n_in,
                              void* d_out, int out_size)
{
    const float* hs   = (const float*)d_in[0];
    const float* enc  = (const float*)d_in[1];
    const float* cosp = (const float*)d_in[2];
    const float* sinp = (const float*)d_in[3];
    const float* wq   = (const float*)d_in[4];
    const float* wk   = (const float*)d_in[5];
    const float* wv   = (const float*)d_in[6];
    const float* wo   = (const float*)d_in[7];
    const float* qnw  = (const float*)d_in[8];
    const float* knw  = (const float*)d_in[9];
    const int*   dmsk = (const int*)d_in[10];
    const int*   emsk = (const int*)d_in[11];
    const int*   pos  = (const int*)d_in[12];
    float* out = (float*)d_out;

    float *gq, *gkv;
    __nv_bfloat16 *ahi, *alo, *whi, *wlo;
    cudaGetSymbolAddress((void**)&gq,  g_q);
    cudaGetSymbolAddress((void**)&gkv, g_kvout);
    cudaGetSymbolAddress((void**)&ahi, g_act_hi);
    cudaGetSymbolAddress((void**)&alo, g_act_lo);
    cudaGetSymbolAddress((void**)&whi, g_wt_hi);
    cudaGetSymbolAddress((void**)&wlo, g_wt_lo);

    cudaFuncSetAttribute(gemm_hmma_kernel,
                         cudaFuncAttributeMaxDynamicSharedMemorySize, GEMM_SMEM);
    cudaFuncSetAttribute(attn2_kernel,
                         cudaFuncAttributeMaxDynamicSharedMemorySize, ATT_SMEM);

    // activation splits: rows 0-2047 decoder, 2048-4095 encoder
    asplit_kernel<<<4096, 256>>>(hs,  ahi,                alo,                2048*2048);
    asplit_kernel<<<4096, 256>>>(enc, ahi + 2048l*2048, alo + 2048l*2048, 2048*2048);

    // q projection
    wsplit_kernel<<<dim3(64, 64), 256>>>(wq, whi, wlo, D_, 2048);
    gemm_hmma_kernel<<<dim3(16, 16), 256, GEMM_SMEM>>>(
        2048, 2048, 2048, ahi, alo, whi, wlo, gq);

    // combined k|v projection over decoder+encoder rows
    wsplit_kernel<<<dim3(32, 64), 256>>>(wk, whi,                 wlo,                 D_, 1024);
    wsplit_kernel<<<dim3(32, 64), 256>>>(wv, whi + 1024l*2048, wlo + 1024l*2048, D_, 1024);
    gemm_hmma_kernel<<<dim3(16, 32), 256, GEMM_SMEM>>>(
        4096, 2048, 2048, ahi, alo, whi, wlo, gkv);

    // metadata + norms (write bf16 splits directly)
    seg_meta_kernel<<<B_, 1024>>>(pos, dmsk, emsk);
    norm_q_kernel<<<2048*8, 256>>>(qnw, cosp, sinp);
    norm_k_kernel<<<4096*4, 256>>>(knw, cosp, sinp);
    vtsplit_kernel<<<dim3(64, 8, B_*KV_), 256>>>();

    // attention (writes bf16 split of output into act rows 0-2047)
    attn2_kernel<<<dim3(S_/64, H_, B_), 128, ATT_SMEM>>>();

    // output projection
    wsplit_kernel<<<dim3(64, 64), 256>>>(wo, whi, wlo, H_*HD_, D_);
    gemm_hmma_kernel<<<dim3(16, 16), 256, GEMM_SMEM>>>(
        2048, 2048, 2048, ahi, alo, whi, wlo, out);
}